// round 12
// baseline (speedup 1.0000x reference)
#include <cuda_runtime.h>
#include <math.h>
#include <stdint.h>

#define NSLICE 1088          // 64 * 17 slices per tensor
#define HW     16384         // 128 * 128
#define MAX_DIST 181.02f
#define NCTA 296             // 2 CTAs/SM
#define NTH  512
#define PF_DIST 3            // prefetch lead, in slices

__device__ float g_acc = 0.0f;       // global loss accumulator (reset by last CTA)
__device__ unsigned int g_done = 0u; // CTA completion counter (reset by last CTA)

__device__ __forceinline__ float fsqrt_approx(float x) {
    float r;
    asm("sqrt.approx.f32 %0, %1;" : "=f"(r) : "f"(x));
    return r;
}
__device__ __forceinline__ float max4(float4 q) {
    return fmaxf(fmaxf(q.x, q.y), fmaxf(q.z, q.w));
}
__device__ __forceinline__ void prefetch_l2(const void* p) {
    asm volatile("prefetch.global.L2 [%0];" :: "l"(p));
}

// ---------------------------------------------------------------------------
// Fused persistent kernel: 2 CTAs/SM x 512 threads. NO smem ring/TMA:
// a per-thread prefetch.global.L2 stream runs PF_DIST slices ahead (DRAM->L2,
// smem-independent lead), pass-1 loads are coalesced LDG.128 into registers
// (L2 hits), and slice m+1's loads are issued BEFORE barrier S3 so their
// latency is covered by the finalize phase. 3 barriers/slice. Value-only max;
// argmax via rare register rescan + shared atomicMin (exact lowest-flat-index
// tie-break). One atomicAdd per CTA; last CTA writes the loss and resets.
// ---------------------------------------------------------------------------
__global__ void __launch_bounds__(NTH, 2) loss_kernel(const float* __restrict__ a,
                                                      const float* __restrict__ b,
                                                      float* __restrict__ out) {
    __shared__ float s_v[16];
    __shared__ float s_s[16];
    __shared__ int   s_c[16];
    __shared__ int   s_idx;

    const int t = threadIdx.x;
    const int warp = t >> 5, lane = t & 31;    // warps 0..15
    const int cta = blockIdx.x;
    const int npair  = (NSLICE - cta + NCTA - 1) / NCTA;   // 3 or 4
    const int nslice = 2 * npair;              // 6 or 8

    // slice m of this CTA: even m -> tensor a, odd m -> tensor b, pair = m>>1
    auto slice_base = [&](int m) -> const float* {
        const float* base = (m & 1) ? b : a;
        return base + (size_t)(cta + (m >> 1) * NCTA) * HW;
    };

    // warm the prefetch pipeline for slices 1..PF_DIST-1
    #pragma unroll
    for (int s = 1; s < PF_DIST; ++s)
        if (s < nslice) prefetch_l2((const char*)slice_base(s) + t * 128);

    // load slice 0 payload (32 elems = 8 float4 per thread)
    float4 v[8];
    {
        const float4* p = (const float4*)slice_base(0);
        #pragma unroll
        for (int j = 0; j < 8; ++j) v[j] = p[j * NTH + t];
    }

    float acc = 0.0f;       // meaningful in t==0 only
    float prev_d = 0.0f;

    for (int m = 0; m < nslice; ++m) {
        // ---------- pass 1: value-only max over registers --------------------
        float mymax = max4(v[0]);
        #pragma unroll
        for (int j = 1; j < 8; ++j) mymax = fmaxf(mymax, max4(v[j]));

        float wmax = mymax;
        #pragma unroll
        for (int off = 16; off > 0; off >>= 1)
            wmax = fmaxf(wmax, __shfl_xor_sync(0xffffffffu, wmax, off));
        if (lane == 0) s_v[warp] = wmax;
        if (t == 0) s_idx = 0x7fffffff;
        __syncthreads();                       // S1

        // block max over the 16 warp maxima, redundantly per warp
        float bv = s_v[lane & 15];
        #pragma unroll
        for (int off = 8; off > 0; off >>= 1)
            bv = fmaxf(bv, __shfl_xor_sync(0xffffffffu, bv, off));

        // rare path: holders of the max rescan registers; lowest flat e wins.
        // e(j, c) = 2048*j + 4*t + c, ascending in j.
        if (mymax == bv) {
            int my_e = 0x7fffffff;
            #pragma unroll
            for (int j = 7; j >= 0; --j) {     // descending: last write = lowest e
                const int eb = (j << 11) + (t << 2);
                if (v[j].w == bv) my_e = eb + 3;
                if (v[j].z == bv) my_e = eb + 2;
                if (v[j].y == bv) my_e = eb + 1;
                if (v[j].x == bv) my_e = eb;
            }
            atomicMin(&s_idx, my_e);
        }
        __syncthreads();                       // S2: s_idx final
        const int bi = s_idx;

        // ---------- pass 2: masked distance sum from registers ---------------
        const float thr = bv * 0.5f;
        const int ym = bi >> 7;
        const int xm = bi & 127;

        // x = 4*lane + c is slice-invariant per thread
        const int xb = (lane << 2) - xm;
        const float fdx2_0 = (float)(xb * xb);
        const float fdx2_1 = (float)((xb + 1) * (xb + 1));
        const float fdx2_2 = (float)((xb + 2) * (xb + 2));
        const float fdx2_3 = (float)((xb + 3) * (xb + 3));

        float sum = 0.0f;
        int   cnt = 0;
        // y(v[j]) = 16*j + warp
        #pragma unroll
        for (int j = 0; j < 8; ++j) {
            const int dy = (j << 4) + warp - ym;
            const float fdy2 = (float)(dy * dy);
            float d0 = fsqrt_approx(fdy2 + fdx2_0);
            float d1 = fsqrt_approx(fdy2 + fdx2_1);
            float d2 = fsqrt_approx(fdy2 + fdx2_2);
            float d3 = fsqrt_approx(fdy2 + fdx2_3);
            if (v[j].x > thr) { sum += d0; ++cnt; }
            if (v[j].y > thr) { sum += d1; ++cnt; }
            if (v[j].z > thr) { sum += d2; ++cnt; }
            if (v[j].w > thr) { sum += d3; ++cnt; }
        }
        #pragma unroll
        for (int off = 16; off > 0; off >>= 1) {
            sum += __shfl_down_sync(0xffffffffu, sum, off);
            cnt += __shfl_down_sync(0xffffffffu, cnt, off);
        }
        if (lane == 0) { s_s[warp] = sum; s_c[warp] = cnt; }

        // keep the DRAM->L2 stream running PF_DIST slices ahead
        if (m + PF_DIST < nslice)
            prefetch_l2((const char*)slice_base(m + PF_DIST) + t * 128);

        // issue next slice's loads BEFORE S3: latency covered by finalize.
        // Registers are thread-private; this slice's uses of v are complete.
        if (m + 1 < nslice) {
            const float4* p = (const float4*)slice_base(m + 1);
            #pragma unroll
            for (int j = 0; j < 8; ++j) v[j] = p[j * NTH + t];
        }
        __syncthreads();                       // S3: all partials written

        // warp 0 reduces; shadowed by other warps starting the next slice
        if (warp == 0) {
            float S = s_s[lane & 15];
            float C = (float)s_c[lane & 15];
            #pragma unroll
            for (int off = 8; off > 0; off >>= 1) {
                S += __shfl_xor_sync(0xffffffffu, S, off);
                C += __shfl_xor_sync(0xffffffffu, C, off);
            }
            if (lane == 0) {
                float d;
                if (bv > 0.0f) {
                    d = (C > 0.0f) ? (S / C) / MAX_DIST : 1.0f;
                } else {
                    d = 0.0f;
                }
                if (m & 1) acc += fabsf(prev_d - d);   // pair done: |d_a - d_b|
                else       prev_d = d;
            }
        }
        // s_v/s_s/s_idx rewrites of the next slice are separated from all
        // reads of this slice by S1..S3 of the next iteration.
    }

    // ---------- fused finalize: one atomic per CTA; last CTA writes + resets
    if (t == 0) {
        atomicAdd(&g_acc, acc);
        __threadfence();
        unsigned int vdone = atomicAdd(&g_done, 1u);
        if (vdone == NCTA - 1) {
            float total = atomicAdd(&g_acc, 0.0f);   // serialized read after all adds
            out[0] = total / 17.0f / 64.0f;
            g_acc = 0.0f;                            // restore invariant for next run
            __threadfence();
            g_done = 0u;
        }
    }
}

extern "C" void kernel_launch(void* const* d_in, const int* in_sizes, int n_in,
                              void* d_out, int out_size) {
    const float* a = (const float*)d_in[0];   // output heatmaps [64,17,128,128] f32
    const float* b = (const float*)d_in[1];   // target heatmaps [64,17,128,128] f32
    (void)in_sizes; (void)n_in; (void)out_size;

    loss_kernel<<<NCTA, NTH>>>(a, b, (float*)d_out);
}

// round 13
// speedup vs baseline: 1.0459x; 1.0459x over previous
#include <cuda_runtime.h>
#include <math.h>
#include <stdint.h>

#define NSLICE 1088          // 64 * 17 slices per tensor
#define HW     16384         // 128 * 128
#define MAX_DIST 181.02f
#define NCTA 296             // 2 CTAs/SM
#define NTH  512
#define CHUNK_FLOATS 8192    // 32 KB chunks, 2 per slice (rows 0-63 / 64-127)
#define CHUNK_BYTES  32768
#define NRING 3              // 96 KB ring per CTA (192 KB/SM with 2 CTAs)
#define PF_SLICES 3          // L2 prefetch lead in slices (DRAM->L2 staging)

__device__ float g_acc = 0.0f;       // global loss accumulator (reset by last CTA)
__device__ unsigned int g_done = 0u; // CTA completion counter (reset by last CTA)

// ---------------------------------------------------------------------------
// mbarrier / bulk-copy / math helpers
// ---------------------------------------------------------------------------
__device__ __forceinline__ uint32_t smem_u32(const void* p) {
    return (uint32_t)__cvta_generic_to_shared(p);
}
__device__ __forceinline__ void mbar_init(uint32_t a, uint32_t cnt) {
    asm volatile("mbarrier.init.shared::cta.b64 [%0], %1;" :: "r"(a), "r"(cnt) : "memory");
}
__device__ __forceinline__ void mbar_arrive_expect(uint32_t a, uint32_t bytes) {
    asm volatile("mbarrier.arrive.expect_tx.shared::cta.b64 _, [%0], %1;"
                 :: "r"(a), "r"(bytes) : "memory");
}
__device__ __forceinline__ void bulk_g2s(uint32_t dst, const void* src,
                                         uint32_t bytes, uint32_t mbar) {
    asm volatile("cp.async.bulk.shared::cta.global.mbarrier::complete_tx::bytes "
                 "[%0], [%1], %2, [%3];"
                 :: "r"(dst), "l"(src), "r"(bytes), "r"(mbar) : "memory");
}
__device__ __forceinline__ void mbar_wait(uint32_t a, uint32_t parity) {
    asm volatile(
        "{\n\t.reg .pred P;\n\t"
        "WAIT_%=:\n\t"
        "mbarrier.try_wait.parity.shared::cta.b64 P, [%0], %1;\n\t"
        "@!P bra WAIT_%=;\n\t}"
        :: "r"(a), "r"(parity) : "memory");
}
__device__ __forceinline__ float fsqrt_approx(float x) {
    float r;
    asm("sqrt.approx.f32 %0, %1;" : "=f"(r) : "f"(x));
    return r;
}
__device__ __forceinline__ float max4(float4 q) {
    return fmaxf(fmaxf(q.x, q.y), fmaxf(q.z, q.w));
}
__device__ __forceinline__ void prefetch_l2(const void* p) {
    asm volatile("prefetch.global.L2 [%0];" :: "l"(p));
}

// ---------------------------------------------------------------------------
// Fused persistent kernel: 2 CTAs/SM x 512 threads, TMA ring transport +
// an L2 staging prefetch stream PF_SLICES ahead. The prefetch moves DRAM->L2
// early; the TMA bulk copy then completes from L2 (~4x lower latency), so the
// shallow 3-slot ring no longer exposes fetch latency. Slice payload (32
// elems) in registers; slots free at the FIRST barrier, refilled by warp 1.
// 3 barriers/slice. Value-only max; argmax via rare register rescan + shared
// atomicMin (exact lowest-flat-index tie-break). One atomicAdd per CTA; last
// CTA writes the loss and resets the globals.
// ---------------------------------------------------------------------------
__global__ void __launch_bounds__(NTH, 2) loss_kernel(const float* __restrict__ a,
                                                      const float* __restrict__ b,
                                                      float* __restrict__ out) {
    extern __shared__ float ring[];            // NRING * 8192 floats (96 KB)

    __shared__ __align__(8) unsigned long long mbar_store[NRING];
    __shared__ float s_v[16];
    __shared__ float s_s[16];
    __shared__ int   s_c[16];
    __shared__ int   s_idx;

    const int t = threadIdx.x;
    const int warp = t >> 5, lane = t & 31;    // warps 0..15
    const int cta = blockIdx.x;
    const int npair  = (NSLICE - cta + NCTA - 1) / NCTA;   // 3 or 4
    const int nslice = 2 * npair;
    const int nchunk = 2 * nslice;                          // 12 or 16

    const uint32_t mb0 = smem_u32(&mbar_store[0]);
    if (t == 0) {
        #pragma unroll
        for (int r = 0; r < NRING; ++r) mbar_init(mb0 + 8u * r, 1);
    }
    __syncthreads();

    // chunk k: pair (k>>2), tensor ((k>>1)&1), half (k&1)
    auto chunk_src = [&](int k) -> const float* {
        int p = k >> 2, which = (k >> 1) & 1, half = k & 1;
        const float* base = which ? b : a;
        return base + (size_t)(cta + p * NCTA) * HW + (size_t)half * CHUNK_FLOATS;
    };
    // slice m: even -> tensor a, odd -> tensor b, pair = m>>1
    auto slice_base = [&](int m) -> const float* {
        const float* base = (m & 1) ? b : a;
        return base + (size_t)(cta + (m >> 1) * NCTA) * HW;
    };

    // warm the L2 staging stream for slices 2..PF_SLICES (ring covers 0-1)
    #pragma unroll
    for (int s = 2; s <= PF_SLICES; ++s)
        if (s < nslice) prefetch_l2((const char*)slice_base(s) + t * 128);

    if (t == 0) {                              // prefill all ring slots
        #pragma unroll
        for (int k = 0; k < NRING; ++k) {
            mbar_arrive_expect(mb0 + 8u * k, CHUNK_BYTES);
            bulk_g2s(smem_u32(ring + k * CHUNK_FLOATS), chunk_src(k),
                     CHUNK_BYTES, mb0 + 8u * k);
        }
    }

    float acc = 0.0f;       // meaningful in t==0 only
    float prev_d = 0.0f;

    for (int m = 0; m < nslice; ++m) {
        const int k0 = 2 * m, k1 = 2 * m + 1;
        const int slot0 = k0 % NRING, slot1 = k1 % NRING;

        // ---------- pass 1: load 32 elems to regs, value-only max ------------
        float4 v[8];
        mbar_wait(mb0 + 8u * slot0, (k0 / NRING) & 1);
        {
            const float4* p = (const float4*)(ring + slot0 * CHUNK_FLOATS);
            v[0] = p[t];            v[1] = p[NTH + t];
            v[2] = p[2 * NTH + t];  v[3] = p[3 * NTH + t];
        }
        mbar_wait(mb0 + 8u * slot1, (k1 / NRING) & 1);
        {
            const float4* p = (const float4*)(ring + slot1 * CHUNK_FLOATS);
            v[4] = p[t];            v[5] = p[NTH + t];
            v[6] = p[2 * NTH + t];  v[7] = p[3 * NTH + t];
        }
        float mymax = max4(v[0]);
        #pragma unroll
        for (int j = 1; j < 8; ++j) mymax = fmaxf(mymax, max4(v[j]));

        float wmax = mymax;
        #pragma unroll
        for (int off = 16; off > 0; off >>= 1)
            wmax = fmaxf(wmax, __shfl_xor_sync(0xffffffffu, wmax, off));
        if (lane == 0) s_v[warp] = wmax;
        if (t == 0) s_idx = 0x7fffffff;

        // keep the L2 staging stream PF_SLICES ahead (fire-and-forget)
        if (m + PF_SLICES < nslice)
            prefetch_l2((const char*)slice_base(m + PF_SLICES) + t * 128);

        __syncthreads();                       // S1: ring slots now free

        // refill freed slots ASAP (warp 1; TMA completes fast from L2)
        if (t == 32) {
            if (k0 + NRING < nchunk) {
                mbar_arrive_expect(mb0 + 8u * slot0, CHUNK_BYTES);
                bulk_g2s(smem_u32(ring + slot0 * CHUNK_FLOATS),
                         chunk_src(k0 + NRING), CHUNK_BYTES, mb0 + 8u * slot0);
            }
            if (k1 + NRING < nchunk) {
                mbar_arrive_expect(mb0 + 8u * slot1, CHUNK_BYTES);
                bulk_g2s(smem_u32(ring + slot1 * CHUNK_FLOATS),
                         chunk_src(k1 + NRING), CHUNK_BYTES, mb0 + 8u * slot1);
            }
        }

        // block max over the 16 warp maxima, redundantly per warp
        float bv = s_v[lane & 15];
        #pragma unroll
        for (int off = 8; off > 0; off >>= 1)
            bv = fmaxf(bv, __shfl_xor_sync(0xffffffffu, bv, off));

        // rare path: holders of the max rescan registers; lowest flat e wins.
        // e(j, c) = (j&3)*2048 + (j>>2)*8192 + 4*t + c, ascending in j.
        if (mymax == bv) {
            int my_e = 0x7fffffff;
            #pragma unroll
            for (int j = 7; j >= 0; --j) {     // descending: last write = lowest e
                const int eb = ((j & 3) << 11) + ((j >> 2) << 13) + (t << 2);
                if (v[j].w == bv) my_e = eb + 3;
                if (v[j].z == bv) my_e = eb + 2;
                if (v[j].y == bv) my_e = eb + 1;
                if (v[j].x == bv) my_e = eb;
            }
            atomicMin(&s_idx, my_e);
        }
        __syncthreads();                       // S2: s_idx final
        const int bi = s_idx;

        // ---------- pass 2: masked distance sum from registers ---------------
        const float thr = bv * 0.5f;
        const int ym = bi >> 7;
        const int xm = bi & 127;

        // x = 4*lane + c is slice-invariant per thread
        const int xb = (lane << 2) - xm;
        const float fdx2_0 = (float)(xb * xb);
        const float fdx2_1 = (float)((xb + 1) * (xb + 1));
        const float fdx2_2 = (float)((xb + 2) * (xb + 2));
        const float fdx2_3 = (float)((xb + 3) * (xb + 3));

        float sum = 0.0f;
        int   cnt = 0;
        // y(v[j]) = 16*j + warp  (j 0..7 spans both chunks contiguously in y)
        #pragma unroll
        for (int j = 0; j < 8; ++j) {
            const int dy = (j << 4) + warp - ym;
            const float fdy2 = (float)(dy * dy);
            float d0 = fsqrt_approx(fdy2 + fdx2_0);
            float d1 = fsqrt_approx(fdy2 + fdx2_1);
            float d2 = fsqrt_approx(fdy2 + fdx2_2);
            float d3 = fsqrt_approx(fdy2 + fdx2_3);
            if (v[j].x > thr) { sum += d0; ++cnt; }
            if (v[j].y > thr) { sum += d1; ++cnt; }
            if (v[j].z > thr) { sum += d2; ++cnt; }
            if (v[j].w > thr) { sum += d3; ++cnt; }
        }
        #pragma unroll
        for (int off = 16; off > 0; off >>= 1) {
            sum += __shfl_down_sync(0xffffffffu, sum, off);
            cnt += __shfl_down_sync(0xffffffffu, cnt, off);
        }
        if (lane == 0) { s_s[warp] = sum; s_c[warp] = cnt; }
        __syncthreads();                       // S3: all partials written

        // warp 0 reduces in parallel; shadowed by other warps entering pass 1
        if (warp == 0) {
            float S = s_s[lane & 15];
            float C = (float)s_c[lane & 15];
            #pragma unroll
            for (int off = 8; off > 0; off >>= 1) {
                S += __shfl_xor_sync(0xffffffffu, S, off);
                C += __shfl_xor_sync(0xffffffffu, C, off);
            }
            if (lane == 0) {
                float d;
                if (bv > 0.0f) {
                    d = (C > 0.0f) ? (S / C) / MAX_DIST : 1.0f;
                } else {
                    d = 0.0f;
                }
                if (m & 1) acc += fabsf(prev_d - d);   // pair done: |d_a - d_b|
                else       prev_d = d;
            }
        }
        // s_v/s_s/s_idx rewrites of the next slice are separated from all
        // reads of this slice by S1..S3 of the next iteration.
    }

    // ---------- fused finalize: one atomic per CTA; last CTA writes + resets
    if (t == 0) {
        atomicAdd(&g_acc, acc);
        __threadfence();
        unsigned int vdone = atomicAdd(&g_done, 1u);
        if (vdone == NCTA - 1) {
            float total = atomicAdd(&g_acc, 0.0f);   // serialized read after all adds
            out[0] = total / 17.0f / 64.0f;
            g_acc = 0.0f;                            // restore invariant for next run
            __threadfence();
            g_done = 0u;
        }
    }
}

extern "C" void kernel_launch(void* const* d_in, const int* in_sizes, int n_in,
                              void* d_out, int out_size) {
    const float* a = (const float*)d_in[0];   // output heatmaps [64,17,128,128] f32
    const float* b = (const float*)d_in[1];   // target heatmaps [64,17,128,128] f32
    (void)in_sizes; (void)n_in; (void)out_size;

    const int smem_bytes = NRING * CHUNK_BYTES;   // 96 KB per CTA

    static bool attr_set = false;
    if (!attr_set) {
        cudaFuncSetAttribute(loss_kernel,
                             cudaFuncAttributeMaxDynamicSharedMemorySize, smem_bytes);
        attr_set = true;
    }

    loss_kernel<<<NCTA, NTH, smem_bytes>>>(a, b, (float*)d_out);
}

// round 14
// speedup vs baseline: 1.0631x; 1.0164x over previous
#include <cuda_runtime.h>
#include <math.h>
#include <stdint.h>

#define NSLICE 1088          // 64 * 17 slices per tensor
#define HW     16384         // 128 * 128
#define MAX_DIST 181.02f
#define NCTA 296             // 2 CTAs/SM
#define NTH  512
#define CHUNK_FLOATS 8192    // 32 KB chunks, 2 per slice (rows 0-63 / 64-127)
#define CHUNK_BYTES  32768
#define NRING 3              // 96 KB ring per CTA (192 KB/SM with 2 CTAs)
#define PF_CHUNKS 6          // TMA-engine L2 prefetch lead: 6 chunks = 3 slices

__device__ float g_acc = 0.0f;       // global loss accumulator (reset by last CTA)
__device__ unsigned int g_done = 0u; // CTA completion counter (reset by last CTA)

// ---------------------------------------------------------------------------
// mbarrier / bulk-copy / math helpers
// ---------------------------------------------------------------------------
__device__ __forceinline__ uint32_t smem_u32(const void* p) {
    return (uint32_t)__cvta_generic_to_shared(p);
}
__device__ __forceinline__ void mbar_init(uint32_t a, uint32_t cnt) {
    asm volatile("mbarrier.init.shared::cta.b64 [%0], %1;" :: "r"(a), "r"(cnt) : "memory");
}
__device__ __forceinline__ void mbar_arrive_expect(uint32_t a, uint32_t bytes) {
    asm volatile("mbarrier.arrive.expect_tx.shared::cta.b64 _, [%0], %1;"
                 :: "r"(a), "r"(bytes) : "memory");
}
__device__ __forceinline__ void bulk_g2s(uint32_t dst, const void* src,
                                         uint32_t bytes, uint32_t mbar) {
    asm volatile("cp.async.bulk.shared::cta.global.mbarrier::complete_tx::bytes "
                 "[%0], [%1], %2, [%3];"
                 :: "r"(dst), "l"(src), "r"(bytes), "r"(mbar) : "memory");
}
// TMA-engine prefetch: one instruction, async DRAM->L2, zero LSU pressure.
__device__ __forceinline__ void bulk_prefetch_l2(const void* src, uint32_t bytes) {
    asm volatile("cp.async.bulk.prefetch.L2.global [%0], %1;"
                 :: "l"(src), "r"(bytes) : "memory");
}
__device__ __forceinline__ void mbar_wait(uint32_t a, uint32_t parity) {
    asm volatile(
        "{\n\t.reg .pred P;\n\t"
        "WAIT_%=:\n\t"
        "mbarrier.try_wait.parity.shared::cta.b64 P, [%0], %1;\n\t"
        "@!P bra WAIT_%=;\n\t}"
        :: "r"(a), "r"(parity) : "memory");
}
__device__ __forceinline__ float fsqrt_approx(float x) {
    float r;
    asm("sqrt.approx.f32 %0, %1;" : "=f"(r) : "f"(x));
    return r;
}
__device__ __forceinline__ float max4(float4 q) {
    return fmaxf(fmaxf(q.x, q.y), fmaxf(q.z, q.w));
}

// ---------------------------------------------------------------------------
// Fused persistent kernel: 2 CTAs/SM x 512 threads (exact R11 structure) +
// a TMA-engine cp.async.bulk.prefetch.L2 stream 3 slices ahead. Demand
// bulk_g2s then completes from L2 instead of DRAM, so the 1.5-slice smem
// ring lead is sufficient. Slice payload (32 elems) in registers; slots free
// at the FIRST barrier, refilled by warp 1. 3 barriers/slice. Value-only max;
// argmax via rare register rescan + shared atomicMin (exact lowest-flat-index
// tie-break). One atomicAdd per CTA; last CTA writes the loss and resets.
// ---------------------------------------------------------------------------
__global__ void __launch_bounds__(NTH, 2) loss_kernel(const float* __restrict__ a,
                                                      const float* __restrict__ b,
                                                      float* __restrict__ out) {
    extern __shared__ float ring[];            // NRING * 8192 floats (96 KB)

    __shared__ __align__(8) unsigned long long mbar_store[NRING];
    __shared__ float s_v[16];
    __shared__ float s_s[16];
    __shared__ int   s_c[16];
    __shared__ int   s_idx;

    const int t = threadIdx.x;
    const int warp = t >> 5, lane = t & 31;    // warps 0..15
    const int cta = blockIdx.x;
    const int npair  = (NSLICE - cta + NCTA - 1) / NCTA;   // 3 or 4
    const int nslice = 2 * npair;
    const int nchunk = 2 * nslice;                          // 12 or 16

    const uint32_t mb0 = smem_u32(&mbar_store[0]);
    if (t == 0) {
        #pragma unroll
        for (int r = 0; r < NRING; ++r) mbar_init(mb0 + 8u * r, 1);
    }
    __syncthreads();

    // chunk k: pair (k>>2), tensor ((k>>1)&1), half (k&1)
    auto chunk_src = [&](int k) -> const float* {
        int p = k >> 2, which = (k >> 1) & 1, half = k & 1;
        const float* base = which ? b : a;
        return base + (size_t)(cta + p * NCTA) * HW + (size_t)half * CHUNK_FLOATS;
    };

    if (t == 0) {
        // warm the L2 staging stream for chunks NRING..PF_CHUNKS-1
        for (int k = NRING; k < PF_CHUNKS && k < nchunk; ++k)
            bulk_prefetch_l2(chunk_src(k), CHUNK_BYTES);
        // prefill all ring slots
        #pragma unroll
        for (int k = 0; k < NRING; ++k) {
            mbar_arrive_expect(mb0 + 8u * k, CHUNK_BYTES);
            bulk_g2s(smem_u32(ring + k * CHUNK_FLOATS), chunk_src(k),
                     CHUNK_BYTES, mb0 + 8u * k);
        }
    }

    float acc = 0.0f;       // meaningful in t==0 only
    float prev_d = 0.0f;

    for (int m = 0; m < nslice; ++m) {
        const int k0 = 2 * m, k1 = 2 * m + 1;
        const int slot0 = k0 % NRING, slot1 = k1 % NRING;

        // ---------- pass 1: load 32 elems to regs, value-only max ------------
        float4 v[8];
        mbar_wait(mb0 + 8u * slot0, (k0 / NRING) & 1);
        {
            const float4* p = (const float4*)(ring + slot0 * CHUNK_FLOATS);
            v[0] = p[t];            v[1] = p[NTH + t];
            v[2] = p[2 * NTH + t];  v[3] = p[3 * NTH + t];
        }
        mbar_wait(mb0 + 8u * slot1, (k1 / NRING) & 1);
        {
            const float4* p = (const float4*)(ring + slot1 * CHUNK_FLOATS);
            v[4] = p[t];            v[5] = p[NTH + t];
            v[6] = p[2 * NTH + t];  v[7] = p[3 * NTH + t];
        }
        float mymax = max4(v[0]);
        #pragma unroll
        for (int j = 1; j < 8; ++j) mymax = fmaxf(mymax, max4(v[j]));

        float wmax = mymax;
        #pragma unroll
        for (int off = 16; off > 0; off >>= 1)
            wmax = fmaxf(wmax, __shfl_xor_sync(0xffffffffu, wmax, off));
        if (lane == 0) s_v[warp] = wmax;
        if (t == 0) s_idx = 0x7fffffff;
        __syncthreads();                       // S1: ring slots now free

        // refill freed slots ASAP (warp 1) + keep the L2 stream 3 slices ahead
        if (t == 32) {
            if (k0 + NRING < nchunk) {
                mbar_arrive_expect(mb0 + 8u * slot0, CHUNK_BYTES);
                bulk_g2s(smem_u32(ring + slot0 * CHUNK_FLOATS),
                         chunk_src(k0 + NRING), CHUNK_BYTES, mb0 + 8u * slot0);
            }
            if (k1 + NRING < nchunk) {
                mbar_arrive_expect(mb0 + 8u * slot1, CHUNK_BYTES);
                bulk_g2s(smem_u32(ring + slot1 * CHUNK_FLOATS),
                         chunk_src(k1 + NRING), CHUNK_BYTES, mb0 + 8u * slot1);
            }
            if (k0 + PF_CHUNKS < nchunk)
                bulk_prefetch_l2(chunk_src(k0 + PF_CHUNKS), CHUNK_BYTES);
            if (k1 + PF_CHUNKS < nchunk)
                bulk_prefetch_l2(chunk_src(k1 + PF_CHUNKS), CHUNK_BYTES);
        }

        // block max over the 16 warp maxima, redundantly per warp
        float bv = s_v[lane & 15];
        #pragma unroll
        for (int off = 8; off > 0; off >>= 1)
            bv = fmaxf(bv, __shfl_xor_sync(0xffffffffu, bv, off));

        // rare path: holders of the max rescan registers; lowest flat e wins.
        // e(j, c) = (j&3)*2048 + (j>>2)*8192 + 4*t + c, ascending in j.
        if (mymax == bv) {
            int my_e = 0x7fffffff;
            #pragma unroll
            for (int j = 7; j >= 0; --j) {     // descending: last write = lowest e
                const int eb = ((j & 3) << 11) + ((j >> 2) << 13) + (t << 2);
                if (v[j].w == bv) my_e = eb + 3;
                if (v[j].z == bv) my_e = eb + 2;
                if (v[j].y == bv) my_e = eb + 1;
                if (v[j].x == bv) my_e = eb;
            }
            atomicMin(&s_idx, my_e);
        }
        __syncthreads();                       // S2: s_idx final
        const int bi = s_idx;

        // ---------- pass 2: masked distance sum from registers ---------------
        const float thr = bv * 0.5f;
        const int ym = bi >> 7;
        const int xm = bi & 127;

        // x = 4*lane + c is slice-invariant per thread
        const int xb = (lane << 2) - xm;
        const float fdx2_0 = (float)(xb * xb);
        const float fdx2_1 = (float)((xb + 1) * (xb + 1));
        const float fdx2_2 = (float)((xb + 2) * (xb + 2));
        const float fdx2_3 = (float)((xb + 3) * (xb + 3));

        float sum = 0.0f;
        int   cnt = 0;
        // y(v[j]) = 16*j + warp  (j 0..7 spans both chunks contiguously in y)
        #pragma unroll
        for (int j = 0; j < 8; ++j) {
            const int dy = (j << 4) + warp - ym;
            const float fdy2 = (float)(dy * dy);
            float d0 = fsqrt_approx(fdy2 + fdx2_0);
            float d1 = fsqrt_approx(fdy2 + fdx2_1);
            float d2 = fsqrt_approx(fdy2 + fdx2_2);
            float d3 = fsqrt_approx(fdy2 + fdx2_3);
            if (v[j].x > thr) { sum += d0; ++cnt; }
            if (v[j].y > thr) { sum += d1; ++cnt; }
            if (v[j].z > thr) { sum += d2; ++cnt; }
            if (v[j].w > thr) { sum += d3; ++cnt; }
        }
        #pragma unroll
        for (int off = 16; off > 0; off >>= 1) {
            sum += __shfl_down_sync(0xffffffffu, sum, off);
            cnt += __shfl_down_sync(0xffffffffu, cnt, off);
        }
        if (lane == 0) { s_s[warp] = sum; s_c[warp] = cnt; }
        __syncthreads();                       // S3: all partials written

        // warp 0 reduces in parallel; shadowed by other warps entering pass 1
        if (warp == 0) {
            float S = s_s[lane & 15];
            float C = (float)s_c[lane & 15];
            #pragma unroll
            for (int off = 8; off > 0; off >>= 1) {
                S += __shfl_xor_sync(0xffffffffu, S, off);
                C += __shfl_xor_sync(0xffffffffu, C, off);
            }
            if (lane == 0) {
                float d;
                if (bv > 0.0f) {
                    d = (C > 0.0f) ? (S / C) / MAX_DIST : 1.0f;
                } else {
                    d = 0.0f;
                }
                if (m & 1) acc += fabsf(prev_d - d);   // pair done: |d_a - d_b|
                else       prev_d = d;
            }
        }
        // s_v/s_s/s_idx rewrites of the next slice are separated from all
        // reads of this slice by S1..S3 of the next iteration.
    }

    // ---------- fused finalize: one atomic per CTA; last CTA writes + resets
    if (t == 0) {
        atomicAdd(&g_acc, acc);
        __threadfence();
        unsigned int vdone = atomicAdd(&g_done, 1u);
        if (vdone == NCTA - 1) {
            float total = atomicAdd(&g_acc, 0.0f);   // serialized read after all adds
            out[0] = total / 17.0f / 64.0f;
            g_acc = 0.0f;                            // restore invariant for next run
            __threadfence();
            g_done = 0u;
        }
    }
}

extern "C" void kernel_launch(void* const* d_in, const int* in_sizes, int n_in,
                              void* d_out, int out_size) {
    const float* a = (const float*)d_in[0];   // output heatmaps [64,17,128,128] f32
    const float* b = (const float*)d_in[1];   // target heatmaps [64,17,128,128] f32
    (void)in_sizes; (void)n_in; (void)out_size;

    const int smem_bytes = NRING * CHUNK_BYTES;   // 96 KB per CTA

    static bool attr_set = false;
    if (!attr_set) {
        cudaFuncSetAttribute(loss_kernel,
                             cudaFuncAttributeMaxDynamicSharedMemorySize, smem_bytes);
        attr_set = true;
    }

    loss_kernel<<<NCTA, NTH, smem_bytes>>>(a, b, (float*)d_out);
}